// round 1
// baseline (speedup 1.0000x reference)
#include <cuda_runtime.h>

// LSTM seq2seq: B=16384, S=T=64, I=4, M=16, H=64
// One persistent kernel. 128 CTAs x 256 threads.
// Each CTA owns 128 batch elements; thread (L, ug) handles element L, units [32*ug, 32*ug+32).
// All state in smem (per-lane columns), weights streamed from gmem via broadcast LDG.

#define NB    16384
#define SEQ   64
#define HID   64

__device__ __forceinline__ float fexp2a(float x) { float y; asm("ex2.approx.f32 %0, %1;" : "=f"(y) : "f"(x)); return y; }
__device__ __forceinline__ float frcpa (float x) { float y; asm("rcp.approx.f32 %0, %1;" : "=f"(y) : "f"(x)); return y; }
// sigmoid(x) = 1/(1+2^(-x*log2e)); abs err ~1e-6
__device__ __forceinline__ float sig_f (float x) { return frcpa(1.0f + fexp2a(-1.4426950408889634f * x)); }
// tanh(x) = 2/(1+2^(-x*2*log2e)) - 1
__device__ __forceinline__ float tanh_f(float x) { return 2.0f * frcpa(1.0f + fexp2a(-2.8853900817779268f * x)) - 1.0f; }

// One LSTM cell update for 32 units of one batch element.
//   gates = Wih @ x + Whh @ h_old + b ; order [i | f | g | o] rows of 64
//   c = sig(f)*c + sig(i)*tanh(g);  h = sig(o)*tanh(c)
// xin_s / hold_s: per-lane float4 columns [k4*128 + L]; c_s: [u*128 + L]
template<int K4>
__device__ __forceinline__ void lstm_cell(
    const float4* __restrict__ Wih4,   // gmem, rows of K4 float4
    const float4* __restrict__ Whh4,   // gmem, rows of 16 float4
    const float*  __restrict__ bias_s, // smem, 256
    const float4* __restrict__ xin_s,  // smem
    const float4* __restrict__ hold_s, // smem
    float*        __restrict__ hnew_s, // smem (float view of float4 layout)
    float*        __restrict__ c_s,    // smem
    int L, int ubase)
{
#pragma unroll 2
    for (int uu = 0; uu < 32; ++uu) {
        const int u = ubase + uu;
        const float4* wi = Wih4 + (size_t)u         * K4;
        const float4* wf = Wih4 + (size_t)(u + 64)  * K4;
        const float4* wg = Wih4 + (size_t)(u + 128) * K4;
        const float4* wo = Wih4 + (size_t)(u + 192) * K4;
        float ai = bias_s[u];
        float af = bias_s[u + 64];
        float ag = bias_s[u + 128];
        float ao = bias_s[u + 192];
        // input part
#pragma unroll 4
        for (int k = 0; k < K4; ++k) {
            float4 x = xin_s[k * 128 + L];
            float4 a = __ldg(wi + k);
            ai += a.x * x.x + a.y * x.y + a.z * x.z + a.w * x.w;
            float4 bq = __ldg(wf + k);
            af += bq.x * x.x + bq.y * x.y + bq.z * x.z + bq.w * x.w;
            float4 cq = __ldg(wg + k);
            ag += cq.x * x.x + cq.y * x.y + cq.z * x.z + cq.w * x.w;
            float4 dq = __ldg(wo + k);
            ao += dq.x * x.x + dq.y * x.y + dq.z * x.z + dq.w * x.w;
        }
        // hidden part (K = 64 always)
        const float4* vi = Whh4 + (size_t)u         * 16;
        const float4* vf = Whh4 + (size_t)(u + 64)  * 16;
        const float4* vg = Whh4 + (size_t)(u + 128) * 16;
        const float4* vo = Whh4 + (size_t)(u + 192) * 16;
#pragma unroll 4
        for (int k = 0; k < 16; ++k) {
            float4 h = hold_s[k * 128 + L];
            float4 a = __ldg(vi + k);
            ai += a.x * h.x + a.y * h.y + a.z * h.z + a.w * h.w;
            float4 bq = __ldg(vf + k);
            af += bq.x * h.x + bq.y * h.y + bq.z * h.z + bq.w * h.w;
            float4 cq = __ldg(vg + k);
            ag += cq.x * h.x + cq.y * h.y + cq.z * h.z + cq.w * h.w;
            float4 dq = __ldg(vo + k);
            ao += dq.x * h.x + dq.y * h.y + dq.z * h.z + dq.w * h.w;
        }
        float c = c_s[u * 128 + L];
        float gi = sig_f(ai);
        float gf = sig_f(af);
        float gg = tanh_f(ag);
        float go = sig_f(ao);
        c = gf * c + gi * gg;
        c_s[u * 128 + L] = c;
        hnew_s[((u >> 2) * 128 + L) * 4 + (u & 3)] = go * tanh_f(c);
    }
}

__global__ void __launch_bounds__(256, 1)
lstm_seq2seq_kernel(
    const float4* __restrict__ src4,   const float4* __restrict__ trg4,
    const float*  __restrict__ W_in,   const float*  __restrict__ b_in,
    const float4* __restrict__ eWih0,  const float4* __restrict__ eWhh0, const float* __restrict__ eb0,
    const float4* __restrict__ eWih1,  const float4* __restrict__ eWhh1, const float* __restrict__ eb1,
    const float4* __restrict__ dWih0,  const float4* __restrict__ dWhh0, const float* __restrict__ db0,
    const float4* __restrict__ dWih1,  const float4* __restrict__ dWhh1, const float* __restrict__ db1,
    const float*  __restrict__ W_out,  const float*  __restrict__ b_out,
    float4*       __restrict__ out4)
{
    extern __shared__ float smem[];
    float* H1A  = smem;          // 8192 floats each (64 x 128)
    float* H1B  = H1A + 8192;
    float* H2A  = H1B + 8192;
    float* H2B  = H2A + 8192;
    float* C1   = H2B + 8192;
    float* C2   = C1  + 8192;
    float* MIDS = C2  + 8192;    // 2048 floats (16 x 128)
    float* SB   = MIDS + 2048;   // consts
    float* s_eb0  = SB;
    float* s_eb1  = SB + 256;
    float* s_db0  = SB + 512;
    float* s_db1  = SB + 768;
    float* s_bin  = SB + 1024;   // 16
    float* s_win  = SB + 1040;   // 64
    float* s_wout = SB + 1104;   // 256
    float* s_bout = SB + 1360;   // 4

    const int tid   = threadIdx.x;
    const int L     = tid & 127;
    const int ug    = tid >> 7;
    const int ubase = ug * 32;
    const int b     = blockIdx.x * 128 + L;

    // init state + consts
    for (int i = tid; i < 8192; i += 256) { H1A[i] = 0.f; H2A[i] = 0.f; C1[i] = 0.f; C2[i] = 0.f; }
    if (tid < 256) {
        s_eb0[tid] = eb0[tid]; s_eb1[tid] = eb1[tid];
        s_db0[tid] = db0[tid]; s_db1[tid] = db1[tid];
        s_wout[tid] = W_out[tid];
    }
    if (tid < 16) s_bin[tid] = b_in[tid];
    if (tid < 64) s_win[tid] = W_in[tid];
    if (tid < 4)  s_bout[tid] = b_out[tid];
    __syncthreads();

    float* h1o = H1A; float* h1n = H1B;
    float* h2o = H2A; float* h2n = H2B;
    float4* MIDS4 = (float4*)MIDS;

    // ================= ENCODER =================
    for (int t = 0; t < SEQ; ++t) {
        float4 x = __ldg(src4 + (size_t)b * SEQ + t);
        // mid = W_in @ x + b_in ; thread computes its 8 m's (two float4 rows)
#pragma unroll
        for (int mg = 0; mg < 2; ++mg) {
            int m0 = ug * 8 + mg * 4;
            float4 v;
            v.x = s_bin[m0+0] + s_win[(m0+0)*4+0]*x.x + s_win[(m0+0)*4+1]*x.y + s_win[(m0+0)*4+2]*x.z + s_win[(m0+0)*4+3]*x.w;
            v.y = s_bin[m0+1] + s_win[(m0+1)*4+0]*x.x + s_win[(m0+1)*4+1]*x.y + s_win[(m0+1)*4+2]*x.z + s_win[(m0+1)*4+3]*x.w;
            v.z = s_bin[m0+2] + s_win[(m0+2)*4+0]*x.x + s_win[(m0+2)*4+1]*x.y + s_win[(m0+2)*4+2]*x.z + s_win[(m0+2)*4+3]*x.w;
            v.w = s_bin[m0+3] + s_win[(m0+3)*4+0]*x.x + s_win[(m0+3)*4+1]*x.y + s_win[(m0+3)*4+2]*x.z + s_win[(m0+3)*4+3]*x.w;
            MIDS4[(m0 >> 2) * 128 + L] = v;
        }
        __syncthreads();
        lstm_cell<4>(eWih0, eWhh0, s_eb0, MIDS4, (const float4*)h1o, h1n, C1, L, ubase);
        __syncthreads();
        lstm_cell<16>(eWih1, eWhh1, s_eb1, (const float4*)h1n, (const float4*)h2o, h2n, C2, L, ubase);
        __syncthreads();
        float* tmp;
        tmp = h1o; h1o = h1n; h1n = tmp;
        tmp = h2o; h2o = h2n; h2n = tmp;
    }

    // ================= DECODER =================
    float4 x = __ldg(trg4 + (size_t)b * SEQ);  // x0 = trg[:,0]
    for (int t = 0; t < SEQ; ++t) {
#pragma unroll
        for (int mg = 0; mg < 2; ++mg) {
            int m0 = ug * 8 + mg * 4;
            float4 v;
            v.x = s_bin[m0+0] + s_win[(m0+0)*4+0]*x.x + s_win[(m0+0)*4+1]*x.y + s_win[(m0+0)*4+2]*x.z + s_win[(m0+0)*4+3]*x.w;
            v.y = s_bin[m0+1] + s_win[(m0+1)*4+0]*x.x + s_win[(m0+1)*4+1]*x.y + s_win[(m0+1)*4+2]*x.z + s_win[(m0+1)*4+3]*x.w;
            v.z = s_bin[m0+2] + s_win[(m0+2)*4+0]*x.x + s_win[(m0+2)*4+1]*x.y + s_win[(m0+2)*4+2]*x.z + s_win[(m0+2)*4+3]*x.w;
            v.w = s_bin[m0+3] + s_win[(m0+3)*4+0]*x.x + s_win[(m0+3)*4+1]*x.y + s_win[(m0+3)*4+2]*x.z + s_win[(m0+3)*4+3]*x.w;
            MIDS4[(m0 >> 2) * 128 + L] = v;
        }
        __syncthreads();
        lstm_cell<4>(dWih0, dWhh0, s_db0, MIDS4, (const float4*)h1o, h1n, C1, L, ubase);
        __syncthreads();
        lstm_cell<16>(dWih1, dWhh1, s_db1, (const float4*)h1n, (const float4*)h2o, h2n, C2, L, ubase);
        __syncthreads();
        // pred = W_out @ h2_new + b_out (computed redundantly in both unit-groups)
        float p0 = s_bout[0], p1 = s_bout[1], p2 = s_bout[2], p3 = s_bout[3];
        const float4* h2n4 = (const float4*)h2n;
#pragma unroll 4
        for (int k = 0; k < 16; ++k) {
            float4 h = h2n4[k * 128 + L];
            p0 += s_wout[0*64 + k*4+0]*h.x + s_wout[0*64 + k*4+1]*h.y + s_wout[0*64 + k*4+2]*h.z + s_wout[0*64 + k*4+3]*h.w;
            p1 += s_wout[1*64 + k*4+0]*h.x + s_wout[1*64 + k*4+1]*h.y + s_wout[1*64 + k*4+2]*h.z + s_wout[1*64 + k*4+3]*h.w;
            p2 += s_wout[2*64 + k*4+0]*h.x + s_wout[2*64 + k*4+1]*h.y + s_wout[2*64 + k*4+2]*h.z + s_wout[2*64 + k*4+3]*h.w;
            p3 += s_wout[3*64 + k*4+0]*h.x + s_wout[3*64 + k*4+1]*h.y + s_wout[3*64 + k*4+2]*h.z + s_wout[3*64 + k*4+3]*h.w;
        }
        float4 tg = __ldg(trg4 + (size_t)b * SEQ + t);
        x.x = p0 + tg.x; x.y = p1 + tg.y; x.z = p2 + tg.z; x.w = p3 + tg.w;
        if (ug == 0) out4[(size_t)b * SEQ + t] = x;  // out = pred + trg
        float* tmp;
        tmp = h1o; h1o = h1n; h1n = tmp;
        tmp = h2o; h2o = h2n; h2n = tmp;
    }
}

extern "C" void kernel_launch(void* const* d_in, const int* in_sizes, int n_in,
                              void* d_out, int out_size)
{
    (void)in_sizes; (void)n_in; (void)out_size;
    const float4* src   = (const float4*)d_in[0];
    const float4* trg   = (const float4*)d_in[1];
    const float*  W_in  = (const float*)d_in[2];
    const float*  b_in  = (const float*)d_in[3];
    const float4* eWih0 = (const float4*)d_in[4];
    const float4* eWhh0 = (const float4*)d_in[5];
    const float*  eb0   = (const float*)d_in[6];
    const float4* eWih1 = (const float4*)d_in[7];
    const float4* eWhh1 = (const float4*)d_in[8];
    const float*  eb1   = (const float*)d_in[9];
    const float4* dWih0 = (const float4*)d_in[10];
    const float4* dWhh0 = (const float4*)d_in[11];
    const float*  db0   = (const float*)d_in[12];
    const float4* dWih1 = (const float4*)d_in[13];
    const float4* dWhh1 = (const float4*)d_in[14];
    const float*  db1   = (const float*)d_in[15];
    const float*  W_out = (const float*)d_in[16];
    const float*  b_out = (const float*)d_in[17];
    float4* out = (float4*)d_out;

    const size_t smem_bytes = (size_t)(6 * 8192 + 2048 + 1364) * sizeof(float); // 210,256 B
    cudaFuncSetAttribute(lstm_seq2seq_kernel,
                         cudaFuncAttributeMaxDynamicSharedMemorySize, (int)smem_bytes);

    lstm_seq2seq_kernel<<<NB / 128, 256, smem_bytes>>>(
        src, trg, W_in, b_in,
        eWih0, eWhh0, eb0, eWih1, eWhh1, eb1,
        dWih0, dWhh0, db0, dWih1, dWhh1, db1,
        W_out, b_out, out);
}

// round 2
// speedup vs baseline: 2.1479x; 2.1479x over previous
#include <cuda_runtime.h>

// LSTM seq2seq: B=16384, S=T=64, I=4, M=16, H=64
// 128 CTAs x 256 threads, persistent. Thread = gate row (weights in registers),
// loop over the CTA's 128 batch elements with broadcast LDS for activations.
// Packed fp32x2 FMA (sm_103a FFMA2) for 2 MACs/instr.

#define SEQ 64

typedef unsigned long long ull;

__device__ __forceinline__ void fma2(ull& d, ull a, ull b) {
    asm("fma.rn.f32x2 %0, %1, %2, %0;" : "+l"(d) : "l"(a), "l"(b));
}
__device__ __forceinline__ float2 unpk(ull v) {
    float2 r; asm("mov.b64 {%0,%1}, %2;" : "=f"(r.x), "=f"(r.y) : "l"(v)); return r;
}
__device__ __forceinline__ float fexp2a(float x) { float y; asm("ex2.approx.f32 %0, %1;" : "=f"(y) : "f"(x)); return y; }
__device__ __forceinline__ float frcpa (float x) { float y; asm("rcp.approx.f32 %0, %1;" : "=f"(y) : "f"(x)); return y; }
__device__ __forceinline__ float sig_f (float x) { return frcpa(1.0f + fexp2a(-1.4426950408889634f * x)); }
__device__ __forceinline__ float tanh_f(float x) { return 2.0f * frcpa(1.0f + fexp2a(-2.8853900817779268f * x)) - 1.0f; }

// smem float offsets
#define OFF_GATES 0        // 256 rows x 65 (padded) = 16640
#define OFF_H1    16640    // 64 x 128 (quad layout [16][128] float4)
#define OFF_H2    24832
#define OFF_C1    33024
#define OFF_C2    41216
#define OFF_MID   49408    // 16 x 128 (quad layout [4][128] float4)
#define OFF_X     51456    // 4 x 128
#define OFF_WIN   51968    // 64
#define OFF_WOUT  52032    // 256
#define OFF_BIN   52288    // 16
#define OFF_BOUT  52304    // 4
#define SMEM_FLOATS 52308

// Gate pre-activation pass: thread r computes row r for 64 batch columns.
// x-part: NXQ float4-quads from Xin; h-part: 16 quads from Hin. Broadcast LDS.
template<int NXQ, int NXP>
__device__ __forceinline__ void gate_pass(
    const ull (&wx)[NXP], const ull (&wh)[32], float bias,
    const float* Xin, const float* Hin, float* GATES, int r, int hb)
{
    const ulonglong2* Xq = (const ulonglong2*)Xin;
    const ulonglong2* Hq = (const ulonglong2*)Hin;
#pragma unroll 1
    for (int b2 = 0; b2 < 64; ++b2) {
        const int b = hb * 64 + b2;
        ull a0 = 0ull, a1 = 0ull;
#pragma unroll
        for (int q = 0; q < NXQ; ++q) {
            ulonglong2 v = Xq[q * 128 + b];
            fma2(a0, wx[2*q],   v.x);
            fma2(a1, wx[2*q+1], v.y);
        }
#pragma unroll
        for (int q = 0; q < 16; ++q) {
            ulonglong2 v = Hq[q * 128 + b];
            fma2(a0, wh[2*q],   v.x);
            fma2(a1, wh[2*q+1], v.y);
        }
        float2 f0 = unpk(a0), f1 = unpk(a1);
        GATES[r * 65 + b2] = f0.x + f0.y + f1.x + f1.y + bias;
    }
}

// Combine pass: thread handles 16 units x 1 batch column of the half-batch.
__device__ __forceinline__ void combine_pass(
    const float* GATES, float* C, float* Hout, int tid, int hb)
{
    const int ugrp = tid >> 6;
    const int b2   = tid & 63;
    const int b    = hb * 64 + b2;
    const int u0   = ugrp * 16;
#pragma unroll
    for (int uu = 0; uu < 16; ++uu) {
        const int u = u0 + uu;
        float gi = GATES[u * 65 + b2];
        float gf = GATES[(u + 64) * 65 + b2];
        float gg = GATES[(u + 128) * 65 + b2];
        float go = GATES[(u + 192) * 65 + b2];
        float c  = C[u * 128 + b];
        c = sig_f(gf) * c + sig_f(gi) * tanh_f(gg);
        C[u * 128 + b] = c;
        Hout[((u >> 2) * 128 + b) * 4 + (u & 3)] = sig_f(go) * tanh_f(c);
    }
}

// One full timestep through both cells (gates + combine, half-batched).
template<int NXP0>
__device__ __forceinline__ void step_cells(
    const ull (&wx0)[NXP0], const ull (&wh0)[32], float bias0,
    const ull (&wx1)[32],   const ull (&wh1)[32], float bias1,
    float* sm, int tid)
{
    float* GATES = sm + OFF_GATES;
    float* H1 = sm + OFF_H1;
    float* H2 = sm + OFF_H2;
    float* C1 = sm + OFF_C1;
    float* C2 = sm + OFF_C2;
    float* MID = sm + OFF_MID;
#pragma unroll 1
    for (int hb = 0; hb < 2; ++hb) {
        gate_pass<NXP0/2>(wx0, wh0, bias0, MID, H1, GATES, tid, hb);
        __syncthreads();
        combine_pass(GATES, C1, H1, tid, hb);
        __syncthreads();
    }
#pragma unroll 1
    for (int hb = 0; hb < 2; ++hb) {
        gate_pass<16>(wx1, wh1, bias1, H1, H2, GATES, tid, hb);
        __syncthreads();
        combine_pass(GATES, C2, H2, tid, hb);
        __syncthreads();
    }
}

// mid = W_in @ x + b_in, written in quad layout [4][128]
__device__ __forceinline__ void mid_rows(float4 x, int b, int half, float* sm)
{
    float* WIN = sm + OFF_WIN;
    float* BIN = sm + OFF_BIN;
    float4* MQ = (float4*)(sm + OFF_MID);
    const int m0 = half * 8;
#pragma unroll
    for (int g = 0; g < 2; ++g) {
        const int m = m0 + g * 4;
        float4 v;
        v.x = BIN[m+0] + WIN[(m+0)*4]*x.x + WIN[(m+0)*4+1]*x.y + WIN[(m+0)*4+2]*x.z + WIN[(m+0)*4+3]*x.w;
        v.y = BIN[m+1] + WIN[(m+1)*4]*x.x + WIN[(m+1)*4+1]*x.y + WIN[(m+1)*4+2]*x.z + WIN[(m+1)*4+3]*x.w;
        v.z = BIN[m+2] + WIN[(m+2)*4]*x.x + WIN[(m+2)*4+1]*x.y + WIN[(m+2)*4+2]*x.z + WIN[(m+2)*4+3]*x.w;
        v.w = BIN[m+3] + WIN[(m+3)*4]*x.x + WIN[(m+3)*4+1]*x.y + WIN[(m+3)*4+2]*x.z + WIN[(m+3)*4+3]*x.w;
        MQ[(m >> 2) * 128 + b] = v;
    }
}

__global__ void __launch_bounds__(256, 1)
lstm_seq2seq_kernel(
    const float4* __restrict__ src4,   const float4* __restrict__ trg4,
    const float*  __restrict__ W_in,   const float*  __restrict__ b_in,
    const float*  __restrict__ eWih0,  const float*  __restrict__ eWhh0, const float* __restrict__ eb0,
    const float*  __restrict__ eWih1,  const float*  __restrict__ eWhh1, const float* __restrict__ eb1,
    const float*  __restrict__ dWih0,  const float*  __restrict__ dWhh0, const float* __restrict__ db0,
    const float*  __restrict__ dWih1,  const float*  __restrict__ dWhh1, const float* __restrict__ db1,
    const float*  __restrict__ W_out,  const float*  __restrict__ b_out,
    float*        __restrict__ out)
{
    extern __shared__ float sm[];
    const int tid = threadIdx.x;
    const int r   = tid;

    // consts
    if (tid < 64)  sm[OFF_WIN  + tid] = W_in[tid];
    if (tid < 256) sm[OFF_WOUT + tid] = W_out[tid];
    if (tid < 16)  sm[OFF_BIN  + tid] = b_in[tid];
    if (tid < 4)   sm[OFF_BOUT + tid] = b_out[tid];
    for (int i = tid; i < 8192; i += 256) {
        sm[OFF_H1 + i] = 0.f; sm[OFF_H2 + i] = 0.f;
        sm[OFF_C1 + i] = 0.f; sm[OFF_C2 + i] = 0.f;
    }
    __syncthreads();

    // weight registers: packed pairs
    ull wx0[8], wh0[32], wx1[32], wh1[32];
    float bias0, bias1;
    {
        const ull* p;
        p = (const ull*)eWih0 + (size_t)r * 8;
#pragma unroll
        for (int m = 0; m < 8; ++m) wx0[m] = p[m];
        p = (const ull*)eWhh0 + (size_t)r * 32;
#pragma unroll
        for (int m = 0; m < 32; ++m) wh0[m] = p[m];
        p = (const ull*)eWih1 + (size_t)r * 32;
#pragma unroll
        for (int m = 0; m < 32; ++m) wx1[m] = p[m];
        p = (const ull*)eWhh1 + (size_t)r * 32;
#pragma unroll
        for (int m = 0; m < 32; ++m) wh1[m] = p[m];
        bias0 = eb0[r]; bias1 = eb1[r];
    }

    const int bcol = tid & 127;
    const int half = tid >> 7;
    const size_t bg = (size_t)(blockIdx.x * 128 + bcol);

    // ================= ENCODER =================
    for (int t = 0; t < SEQ; ++t) {
        float4 x = __ldg(src4 + bg * SEQ + t);
        mid_rows(x, bcol, half, sm);
        __syncthreads();
        step_cells(wx0, wh0, bias0, wx1, wh1, bias1, sm, tid);
    }

    // reload decoder weights into the same registers
    {
        const ull* p;
        p = (const ull*)dWih0 + (size_t)r * 8;
#pragma unroll
        for (int m = 0; m < 8; ++m) wx0[m] = p[m];
        p = (const ull*)dWhh0 + (size_t)r * 32;
#pragma unroll
        for (int m = 0; m < 32; ++m) wh0[m] = p[m];
        p = (const ull*)dWih1 + (size_t)r * 32;
#pragma unroll
        for (int m = 0; m < 32; ++m) wx1[m] = p[m];
        p = (const ull*)dWhh1 + (size_t)r * 32;
#pragma unroll
        for (int m = 0; m < 32; ++m) wh1[m] = p[m];
        bias0 = db0[r]; bias1 = db1[r];
    }

    // X init = trg[:,0]
    if (tid < 128) {
        float4 tg = __ldg(trg4 + bg * SEQ);
        sm[OFF_X +   0 + bcol] = tg.x;
        sm[OFF_X + 128 + bcol] = tg.y;
        sm[OFF_X + 256 + bcol] = tg.z;
        sm[OFF_X + 384 + bcol] = tg.w;
    }
    __syncthreads();

    // ================= DECODER =================
    for (int t = 0; t < SEQ; ++t) {
        float4 x;
        x.x = sm[OFF_X +   0 + bcol];
        x.y = sm[OFF_X + 128 + bcol];
        x.z = sm[OFF_X + 256 + bcol];
        x.w = sm[OFF_X + 384 + bcol];
        mid_rows(x, bcol, half, sm);
        __syncthreads();
        step_cells(wx0, wh0, bias0, wx1, wh1, bias1, sm, tid);

        // pred = W_out @ h2 + b_out; X_next = pred + trg[:,t]; out[:,t] = X_next
        {
            const int o = half * 2;
            const float* WOUT = sm + OFF_WOUT;
            const float4* H2q = (const float4*)(sm + OFF_H2);
            float p0 = sm[OFF_BOUT + o], p1 = sm[OFF_BOUT + o + 1];
#pragma unroll
            for (int q = 0; q < 16; ++q) {
                float4 h = H2q[q * 128 + bcol];
                p0 += WOUT[o*64 + q*4]*h.x + WOUT[o*64 + q*4+1]*h.y + WOUT[o*64 + q*4+2]*h.z + WOUT[o*64 + q*4+3]*h.w;
                p1 += WOUT[(o+1)*64 + q*4]*h.x + WOUT[(o+1)*64 + q*4+1]*h.y + WOUT[(o+1)*64 + q*4+2]*h.z + WOUT[(o+1)*64 + q*4+3]*h.w;
            }
            float2 tg = __ldg((const float2*)trg4 + (bg * SEQ + t) * 2 + half);
            float xo0 = p0 + tg.x;
            float xo1 = p1 + tg.y;
            sm[OFF_X + o * 128 + bcol]       = xo0;
            sm[OFF_X + (o + 1) * 128 + bcol] = xo1;
            ((float2*)out)[(bg * SEQ + t) * 2 + half] = make_float2(xo0, xo1);
        }
        __syncthreads();
    }
}

extern "C" void kernel_launch(void* const* d_in, const int* in_sizes, int n_in,
                              void* d_out, int out_size)
{
    (void)in_sizes; (void)n_in; (void)out_size;
    const float4* src   = (const float4*)d_in[0];
    const float4* trg   = (const float4*)d_in[1];
    const float*  W_in  = (const float*)d_in[2];
    const float*  b_in  = (const float*)d_in[3];
    const float*  eWih0 = (const float*)d_in[4];
    const float*  eWhh0 = (const float*)d_in[5];
    const float*  eb0   = (const float*)d_in[6];
    const float*  eWih1 = (const float*)d_in[7];
    const float*  eWhh1 = (const float*)d_in[8];
    const float*  eb1   = (const float*)d_in[9];
    const float*  dWih0 = (const float*)d_in[10];
    const float*  dWhh0 = (const float*)d_in[11];
    const float*  db0   = (const float*)d_in[12];
    const float*  dWih1 = (const float*)d_in[13];
    const float*  dWhh1 = (const float*)d_in[14];
    const float*  db1   = (const float*)d_in[15];
    const float*  W_out = (const float*)d_in[16];
    const float*  b_out = (const float*)d_in[17];
    float* out = (float*)d_out;

    const size_t smem_bytes = (size_t)SMEM_FLOATS * sizeof(float); // 209,232 B
    cudaFuncSetAttribute(lstm_seq2seq_kernel,
                         cudaFuncAttributeMaxDynamicSharedMemorySize, (int)smem_bytes);

    lstm_seq2seq_kernel<<<128, 256, smem_bytes>>>(
        src, trg, W_in, b_in,
        eWih0, eWhh0, eb0, eWih1, eWhh1, eb1,
        dWih0, dWhh0, db0, dWih1, dWhh1, db1,
        W_out, b_out, out);
}